// round 2
// baseline (speedup 1.0000x reference)
#include <cuda_runtime.h>
#include <cstdint>
#include <cstddef>

// ============================================================================
// RhythmMemoryUpdater — GB300 sm_103a (toolchain targets sm_103 base: no tcgen05)
//   L = 1  =>  out = node_memories; out[node_ids] = LN( x @ W'^T + lin_b )
//   x = [messages | node_memories[node_ids]] (K=256)
//   W'[d,c] = lin_w[d,c] * conv_w[c, period/2]
// Kernel 1: full copy node_memories -> out (streaming float4)
// Kernel 2: persistent HMMA (mma.sync m16n8k8 tf32) GEMM + bias + LN + scatter
// ============================================================================

#define NDIM 128           // output dim / mem dim / msg dim
#define KDIM 256
#define TILE_M 64          // rows per CTA iteration
#define NTHREADS 256

#define SW_STRIDE 264      // W' smem row stride (floats), pad 8
#define SX_STRIDE 260      // x  smem row stride (floats), pad 4
#define SD_STRIDE 132      // D  smem row stride (floats), pad 4

__device__ __forceinline__ uint32_t f2tf32(float f) {
    uint32_t o;
    asm("cvt.rna.tf32.f32 %0, %1;" : "=r"(o) : "f"(f));
    return o;
}

__device__ __forceinline__ void mma_tf32(float c[4], uint32_t a0, uint32_t a1,
                                         uint32_t a2, uint32_t a3,
                                         uint32_t b0, uint32_t b1) {
    asm volatile(
        "mma.sync.aligned.m16n8k8.row.col.f32.tf32.tf32.f32 "
        "{%0,%1,%2,%3}, {%4,%5,%6,%7}, {%8,%9}, {%0,%1,%2,%3};"
        : "+f"(c[0]), "+f"(c[1]), "+f"(c[2]), "+f"(c[3])
        : "r"(a0), "r"(a1), "r"(a2), "r"(a3), "r"(b0), "r"(b1));
}

// ============================================================================
// Kernel 1: bulk copy node_memories -> out
// ============================================================================
__global__ void __launch_bounds__(256) copy_kernel(const float4* __restrict__ src,
                                                   float4* __restrict__ dst,
                                                   long long n) {
    long long i = (long long)blockIdx.x * blockDim.x + threadIdx.x;
    long long stride = (long long)gridDim.x * blockDim.x;
    for (; i < n; i += stride) dst[i] = src[i];
}

// ============================================================================
// Kernel 2: persistent GEMM + LayerNorm + scatter
//   smem: sW (128 x SW_STRIDE, tf32 bits, k-pair-permuted)
//         sX (64 x SX_STRIDE, tf32 bits)  -- reused as D (64 x SD_STRIDE, f32)
// ============================================================================
__global__ void __launch_bounds__(NTHREADS, 1) rhythm_kernel(
    const int*   __restrict__ node_ids,
    const float* __restrict__ messages,
    const float* __restrict__ node_mem,
    const float* __restrict__ conv_w,
    const float* __restrict__ lin_w,
    const float* __restrict__ lin_b,
    const float* __restrict__ ln_g,
    const float* __restrict__ ln_bt,
    float*       __restrict__ out,
    int ntiles, int conv_stride, int conv_col)
{
    extern __shared__ uint32_t smem_u[];
    uint32_t* sW = smem_u;                      // 128 * SW_STRIDE
    uint32_t* sX = smem_u + NDIM * SW_STRIDE;   // 64 * SX_STRIDE
    float*    sD = (float*)sX;                  // aliased, guarded by syncs

    __shared__ float s_wcol[KDIM];
    __shared__ float s_bias[NDIM], s_gamma[NDIM], s_beta[NDIM];
    __shared__ int   s_node[TILE_M];

    const int tid  = threadIdx.x;
    const int lane = tid & 31;
    const int wid  = tid >> 5;

    // ---- stage small vectors ----
    if (tid < KDIM) s_wcol[tid] = conv_w[tid * conv_stride + conv_col];
    if (tid < NDIM) {
        s_bias[tid]  = lin_b[tid];
        s_gamma[tid] = ln_g[tid];
        s_beta[tid]  = ln_bt[tid];
    }
    __syncthreads();

    // ---- build W' in smem (tf32 bits), k-pair permuted so that the B-fragment
    //      pair (k, k+4) of each 8-k group is contiguous (one LDS.64) ----
    //      kperm(c) = (c & ~7) + (c & 3) * 2 + ((c >> 2) & 1)
    for (int idx = tid; idx < NDIM * KDIM; idx += NTHREADS) {
        int d = idx >> 8, c = idx & 255;
        float v = lin_w[idx] * s_wcol[c];
        int kperm = (c & ~7) + ((c & 3) << 1) + ((c >> 2) & 1);
        sW[d * SW_STRIDE + kperm] = f2tf32(v);
    }

    // per-warp tile geometry: rows mt..mt+15, cols nh..nh+63
    const int mt = (wid & 3) * 16;
    const int nh = (wid >> 2) * 64;

    for (int tile = blockIdx.x; tile < ntiles; tile += gridDim.x) {
        __syncthreads();  // W' ready (first iter) / previous D consumed

        // ---- load node ids for this tile ----
        if (tid < TILE_M) s_node[tid] = node_ids[tile * TILE_M + tid];
        __syncthreads();

        // ---- stage x = [messages | gathered mem] as tf32 bits ----
        // 64 rows x 32 float4 per half
        {
            const float4* msg4 = (const float4*)(messages + (size_t)tile * TILE_M * NDIM);
#pragma unroll
            for (int i = 0; i < 8; i++) {
                int idx = i * NTHREADS + tid;        // 0..2047
                int row = idx >> 5, c4 = idx & 31;
                float4 t = msg4[idx];
                uint32_t* d = &sX[row * SX_STRIDE + c4 * 4];
                d[0] = f2tf32(t.x); d[1] = f2tf32(t.y);
                d[2] = f2tf32(t.z); d[3] = f2tf32(t.w);
            }
#pragma unroll
            for (int i = 0; i < 8; i++) {
                int idx = i * NTHREADS + tid;
                int row = idx >> 5, c4 = idx & 31;
                const float4* src = (const float4*)(node_mem + (size_t)s_node[row] * NDIM);
                float4 t = src[c4];
                uint32_t* d = &sX[row * SX_STRIDE + NDIM + c4 * 4];
                d[0] = f2tf32(t.x); d[1] = f2tf32(t.y);
                d[2] = f2tf32(t.z); d[3] = f2tf32(t.w);
            }
        }
        __syncthreads();

        // ---- GEMM: per warp 16 rows x 64 cols, K=256 via 32 k-tiles ----
        float c[8][4];
#pragma unroll
        for (int nt = 0; nt < 8; nt++)
#pragma unroll
            for (int j = 0; j < 4; j++) c[nt][j] = 0.f;

        const int r0 = mt + (lane >> 2);
        const int k0 = lane & 3;
        const uint32_t* xa = &sX[r0 * SX_STRIDE];
        const uint32_t* xb = &sX[(r0 + 8) * SX_STRIDE];
        const int bn = nh + (lane >> 2);   // base n for this lane's B fragment

#pragma unroll 4
        for (int kt = 0; kt < 32; kt++) {
            int kk = kt * 8 + k0;
            uint32_t a0 = xa[kk];
            uint32_t a1 = xb[kk];
            uint32_t a2 = xa[kk + 4];
            uint32_t a3 = xb[kk + 4];
#pragma unroll
            for (int nt = 0; nt < 8; nt++) {
                const uint2 b = *(const uint2*)&sW[(bn + nt * 8) * SW_STRIDE + kt * 8 + (k0 << 1)];
                mma_tf32(c[nt], a0, a1, a2, a3, b.x, b.y);
            }
        }
        __syncthreads();  // all sX reads done before D overwrites the buffer

        // ---- write D fragments to smem ----
        {
            const int dr0 = mt + (lane >> 2);
            const int dc  = nh + ((lane & 3) << 1);
#pragma unroll
            for (int nt = 0; nt < 8; nt++) {
                *(float2*)&sD[dr0 * SD_STRIDE + dc + nt * 8]       = make_float2(c[nt][0], c[nt][1]);
                *(float2*)&sD[(dr0 + 8) * SD_STRIDE + dc + nt * 8] = make_float2(c[nt][2], c[nt][3]);
            }
        }
        __syncthreads();

        // ---- epilogue: bias + LayerNorm + scatter ----
        {
            const int row = tid >> 2;       // 0..63
            const int q   = tid & 3;        // quarter: 32 cols
            const int cb  = q * 32;
            float vals[32];
            float vsum = 0.f, vsq = 0.f;
            const float* drow = &sD[row * SD_STRIDE + cb];
#pragma unroll
            for (int j = 0; j < 32; j++) {
                float v = drow[j] + s_bias[cb + j];
                vals[j] = v;
                vsum += v;
                vsq  += v * v;
            }
            vsum += __shfl_xor_sync(0xffffffffu, vsum, 1);
            vsum += __shfl_xor_sync(0xffffffffu, vsum, 2);
            vsq  += __shfl_xor_sync(0xffffffffu, vsq, 1);
            vsq  += __shfl_xor_sync(0xffffffffu, vsq, 2);
            float mean = vsum * (1.0f / 128.0f);
            float var  = vsq * (1.0f / 128.0f) - mean * mean;
            float rstd = rsqrtf(var + 1e-5f);

            float4* dst = (float4*)(out + (size_t)s_node[row] * NDIM + cb);
#pragma unroll
            for (int j = 0; j < 8; j++) {
                float4 o;
                o.x = (vals[4*j + 0] - mean) * rstd * s_gamma[cb + 4*j + 0] + s_beta[cb + 4*j + 0];
                o.y = (vals[4*j + 1] - mean) * rstd * s_gamma[cb + 4*j + 1] + s_beta[cb + 4*j + 1];
                o.z = (vals[4*j + 2] - mean) * rstd * s_gamma[cb + 4*j + 2] + s_beta[cb + 4*j + 2];
                o.w = (vals[4*j + 3] - mean) * rstd * s_gamma[cb + 4*j + 3] + s_beta[cb + 4*j + 3];
                dst[j] = o;
            }
        }
    }
}

// ============================================================================
// launch
// ============================================================================
extern "C" void kernel_launch(void* const* d_in, const int* in_sizes, int n_in,
                              void* d_out, int out_size) {
    const int*   node_ids = (const int*)  d_in[0];
    const float* messages = (const float*)d_in[1];
    const float* node_mem = (const float*)d_in[2];
    const float* conv_w   = (const float*)d_in[3];
    const float* lin_w    = (const float*)d_in[4];
    const float* lin_b    = (const float*)d_in[5];
    const float* ln_g     = (const float*)d_in[6];
    const float* ln_bt    = (const float*)d_in[7];
    float* out = (float*)d_out;

    int Btot     = in_sizes[1] / NDIM;     // 262144 rows
    int ntiles   = Btot / TILE_M;          // 4096
    int period   = in_sizes[3] / KDIM;     // 7
    int conv_col = period / 2;             // pad = 3 (L == 1 path)

    // 1) out = node_memories (full copy; compute kernel overwrites scattered rows)
    copy_kernel<<<2048, 256>>>((const float4*)node_mem, (float4*)out,
                               (long long)out_size / 4);

    // 2) persistent GEMM + LN + scatter
    const int dyn_smem = (NDIM * SW_STRIDE + TILE_M * SX_STRIDE) * 4;  // ~202 KB
    static int configured = -1;
    if (configured != dyn_smem) {
        cudaFuncSetAttribute(rhythm_kernel, cudaFuncAttributeMaxDynamicSharedMemorySize,
                             dyn_smem);
        configured = dyn_smem;
    }
    rhythm_kernel<<<148, NTHREADS, dyn_smem>>>(node_ids, messages, node_mem, conv_w,
                                               lin_w, lin_b, ln_g, ln_bt, out,
                                               ntiles, period, conv_col);
}